// round 3
// baseline (speedup 1.0000x reference)
#include <cuda_runtime.h>

namespace {
constexpr int Bsz  = 512;
constexpr int Tlen = 4096;
constexpr int IN   = 8;
constexpr int H    = 64;
constexpr int NB   = 4;          // batch elements per block
constexpr int NTHR = 256;        // 64 j-units x 4 k-splits
constexpr int NBLK = Bsz / NB;   // 128

__device__ __forceinline__ float tanh_fast(float x) {
  float y;
  asm("tanh.approx.f32 %0, %1;" : "=f"(y) : "f"(x));
  return y;
}
__device__ __forceinline__ float sigmoid_fast(float x) {
  return fmaf(0.5f, tanh_fast(0.5f * x), 0.5f);
}
__device__ __forceinline__ unsigned long long splat2(float w) {
  unsigned long long r;
  asm("mov.b64 %0, {%1, %1};" : "=l"(r) : "f"(w));
  return r;
}
__device__ __forceinline__ void ffma2(unsigned long long& acc,
                                      unsigned long long a,
                                      unsigned long long b) {
  asm("fma.rn.f32x2 %0, %1, %2, %0;" : "+l"(acc) : "l"(a), "l"(b));
}
__device__ __forceinline__ void unpack2(unsigned long long v, float& lo, float& hi) {
  asm("mov.b64 {%0, %1}, %2;" : "=f"(lo), "=f"(hi) : "l"(v));
}
}  // namespace

__global__ __launch_bounds__(NTHR, 1) void lstm2_jown_kernel(
    const float* __restrict__ x,
    const float* __restrict__ Wih0, const float* __restrict__ Whh0,
    const float* __restrict__ bih0, const float* __restrict__ bhh0,
    const float* __restrict__ Wih1, const float* __restrict__ Whh1,
    const float* __restrict__ bih1, const float* __restrict__ bhh1,
    const float* __restrict__ fcw, const float* __restrict__ fcb,
    float* __restrict__ out) {
  __shared__ __align__(16) float hcat[2 * H][NB];  // rows 0..63 h0, 64..127 h1
  __shared__ __align__(16) float xbuf[2][IN][NB];  // double-buffered x[t]
  __shared__ float fcw_s[H];

  const int tid = threadIdx.x;
  const int b0  = blockIdx.x * NB;
  const int j   = tid >> 2;  // hidden unit 0..63  (owns gates j, j+64, j+128, j+192)
  const int s   = tid & 3;   // k-split 0..3 (same-warp partners via lane bits 0-1)

  // ---- register-resident weights (per thread: 4 gates, this thread's k slice) ----
  float w0[4][16];  // Whh0, k = s*16 + kk
  float wx[4][2];   // Wih0, i = s*2 + ii
  float w1[4][32];  // [Wih1|Whh1] concat, k = s*32 + kk
  float bs0[4], bs1[4];
  {
    const float* base1 = (s < 2) ? Wih1 : Whh1;
    const int kb1 = (s * 32) & 63;
#pragma unroll
    for (int qg = 0; qg < 4; ++qg) {
      const int g = qg * 64 + j;
#pragma unroll
      for (int kk = 0; kk < 16; ++kk) w0[qg][kk] = Whh0[g * H + s * 16 + kk];
#pragma unroll
      for (int ii = 0; ii < 2; ++ii) wx[qg][ii] = Wih0[g * IN + s * 2 + ii];
#pragma unroll
      for (int kk = 0; kk < 32; ++kk) w1[qg][kk] = base1[g * H + kb1 + kk];
      bs0[qg] = bih0[g] + bhh0[g];
      bs1[qg] = bih1[g] + bhh1[g];
    }
  }

  // ---- shared staging ----
  if (tid < H) fcw_s[tid] = fcw[tid];
  for (int idx = tid; idx < 2 * H * NB; idx += NTHR) (&hcat[0][0])[idx] = 0.0f;
  if (tid < NB * IN) {  // x[t=0]
    int b = tid >> 3, i = tid & 7;
    xbuf[0][i][b] = x[(b0 + b) * Tlen * IN + i];
  }
  __syncthreads();

  float c0 = 0.0f, c1 = 0.0f;  // cell state for (j, batch s)
  int cur = 0;

#pragma unroll 1
  for (int t = 0; t < Tlen; ++t) {
    // prefetch next x slice (warp 0)
    float xn = 0.0f;
    const bool isLoader = (tid < NB * IN) && (t + 1 < Tlen);
    if (isLoader) {
      xn = __ldg(&x[((b0 + (tid >> 3)) * Tlen + (t + 1)) * IN + (tid & 7)]);
    }

    // ============ layer 0: gates (partial over this thread's k slice) ============
    unsigned long long a01[4] = {0, 0, 0, 0}, a23[4] = {0, 0, 0, 0};
#pragma unroll
    for (int ii = 0; ii < 2; ++ii) {
      ulonglong2 v = *reinterpret_cast<const ulonglong2*>(&xbuf[cur][s * 2 + ii][0]);
#pragma unroll
      for (int qg = 0; qg < 4; ++qg) {
        unsigned long long W = splat2(wx[qg][ii]);
        ffma2(a01[qg], W, v.x);
        ffma2(a23[qg], W, v.y);
      }
    }
#pragma unroll
    for (int kk = 0; kk < 16; ++kk) {
      ulonglong2 v = *reinterpret_cast<const ulonglong2*>(&hcat[s * 16 + kk][0]);
#pragma unroll
      for (int qg = 0; qg < 4; ++qg) {
        unsigned long long W = splat2(w0[qg][kk]);
        ffma2(a01[qg], W, v.x);
        ffma2(a23[qg], W, v.y);
      }
    }
    // in-warp reduction across s (lane bits 0-1), then lane s keeps batch s
    {
      float gv[4];
#pragma unroll
      for (int qg = 0; qg < 4; ++qg) {
        float l0, h0v, l1, h1v;
        unpack2(a01[qg], l0, h0v);
        unpack2(a23[qg], l1, h1v);
        l0  += __shfl_xor_sync(0xffffffffu, l0, 1);
        h0v += __shfl_xor_sync(0xffffffffu, h0v, 1);
        l1  += __shfl_xor_sync(0xffffffffu, l1, 1);
        h1v += __shfl_xor_sync(0xffffffffu, h1v, 1);
        l0  += __shfl_xor_sync(0xffffffffu, l0, 2);
        h0v += __shfl_xor_sync(0xffffffffu, h0v, 2);
        l1  += __shfl_xor_sync(0xffffffffu, l1, 2);
        h1v += __shfl_xor_sync(0xffffffffu, h1v, 2);
        gv[qg] = (s == 0) ? l0 : (s == 1) ? h0v : (s == 2) ? l1 : h1v;
      }
      float gi = sigmoid_fast(gv[0] + bs0[0]);
      float gf = sigmoid_fast(gv[1] + bs0[1]);
      float gg = tanh_fast(gv[2] + bs0[2]);
      float go = sigmoid_fast(gv[3] + bs0[3]);
      c0 = fmaf(gf, c0, gi * gg);
      hcat[j][s] = go * tanh_fast(c0);  // conflict-free: bank = tid mod 32
    }
    __syncthreads();

    // ============ layer 1: gates over [h0; h1] ============
    unsigned long long d01[4] = {0, 0, 0, 0}, d23[4] = {0, 0, 0, 0};
#pragma unroll
    for (int kk = 0; kk < 32; ++kk) {
      ulonglong2 v = *reinterpret_cast<const ulonglong2*>(&hcat[s * 32 + kk][0]);
#pragma unroll
      for (int qg = 0; qg < 4; ++qg) {
        unsigned long long W = splat2(w1[qg][kk]);
        ffma2(d01[qg], W, v.x);
        ffma2(d23[qg], W, v.y);
      }
    }
    if (isLoader) {
      xbuf[cur ^ 1][tid & 7][tid >> 3] = xn;
    }
    {
      float gv[4];
#pragma unroll
      for (int qg = 0; qg < 4; ++qg) {
        float l0, h0v, l1, h1v;
        unpack2(d01[qg], l0, h0v);
        unpack2(d23[qg], l1, h1v);
        l0  += __shfl_xor_sync(0xffffffffu, l0, 1);
        h0v += __shfl_xor_sync(0xffffffffu, h0v, 1);
        l1  += __shfl_xor_sync(0xffffffffu, l1, 1);
        h1v += __shfl_xor_sync(0xffffffffu, h1v, 1);
        l0  += __shfl_xor_sync(0xffffffffu, l0, 2);
        h0v += __shfl_xor_sync(0xffffffffu, h0v, 2);
        l1  += __shfl_xor_sync(0xffffffffu, l1, 2);
        h1v += __shfl_xor_sync(0xffffffffu, h1v, 2);
        gv[qg] = (s == 0) ? l0 : (s == 1) ? h0v : (s == 2) ? l1 : h1v;
      }
      float gi = sigmoid_fast(gv[0] + bs1[0]);
      float gf = sigmoid_fast(gv[1] + bs1[1]);
      float gg = tanh_fast(gv[2] + bs1[2]);
      float go = sigmoid_fast(gv[3] + bs1[3]);
      c1 = fmaf(gf, c1, gi * gg);
      hcat[H + j][s] = go * tanh_fast(c1);
    }
    __syncthreads();
    cur ^= 1;
  }

  // ---- epilogue: FC + sigmoid on last h1 ----
  if (tid < NB) {
    float acc = fcb[0];
#pragma unroll 16
    for (int jj = 0; jj < H; ++jj) acc = fmaf(hcat[H + jj][tid], fcw_s[jj], acc);
    out[b0 + tid] = 1.0f / (1.0f + __expf(-acc));
  }
}

extern "C" void kernel_launch(void* const* d_in, const int* in_sizes, int n_in,
                              void* d_out, int out_size) {
  const float* x    = (const float*)d_in[0];
  const float* Wih0 = (const float*)d_in[1];
  const float* Whh0 = (const float*)d_in[2];
  const float* bih0 = (const float*)d_in[3];
  const float* bhh0 = (const float*)d_in[4];
  const float* Wih1 = (const float*)d_in[5];
  const float* Whh1 = (const float*)d_in[6];
  const float* bih1 = (const float*)d_in[7];
  const float* bhh1 = (const float*)d_in[8];
  const float* fcw  = (const float*)d_in[9];
  const float* fcb  = (const float*)d_in[10];
  float* out = (float*)d_out;

  lstm2_jown_kernel<<<NBLK, NTHR>>>(x, Wih0, Whh0, bih0, bhh0, Wih1, Whh1,
                                    bih1, bhh1, fcw, fcb, out);
}

// round 5
// speedup vs baseline: 2.2442x; 2.2442x over previous
#include <cuda_runtime.h>

namespace {
constexpr int Bsz  = 512;
constexpr int Tlen = 4096;
constexpr int IN   = 8;
constexpr int H    = 64;
constexpr int NB   = 4;
constexpr int NTHR = 512;        // 64 units x 8 k-splits
constexpr int NBLK = Bsz / NB;   // 128

using u64 = unsigned long long;

__device__ __forceinline__ float tanh_fast(float x) {
  float y;
  asm("tanh.approx.f32 %0, %1;" : "=f"(y) : "f"(x));
  return y;
}
__device__ __forceinline__ float sigmoid_fast(float x) {
  return fmaf(0.5f, tanh_fast(0.5f * x), 0.5f);
}
__device__ __forceinline__ u64 splat2(float w) {
  u64 r;
  asm("mov.b64 %0, {%1, %1};" : "=l"(r) : "f"(w));
  return r;
}
__device__ __forceinline__ void ffma2(u64& acc, u64 a, u64 b) {
  asm("fma.rn.f32x2 %0, %1, %2, %0;" : "+l"(acc) : "l"(a), "l"(b));
}
__device__ __forceinline__ u64 add2(u64 a, u64 b) {
  u64 r;
  asm("add.rn.f32x2 %0, %1, %2;" : "=l"(r) : "l"(a), "l"(b));
  return r;
}
__device__ __forceinline__ void unpack2(u64 v, float& lo, float& hi) {
  asm("mov.b64 {%0, %1}, %2;" : "=f"(lo), "=f"(hi) : "l"(v));
}
__device__ __forceinline__ u64 shfl64x(u64 v, int m) {
  float a, b;
  unpack2(v, a, b);
  a = __shfl_xor_sync(0xffffffffu, a, m);
  b = __shfl_xor_sync(0xffffffffu, b, m);
  u64 r;
  asm("mov.b64 %0, {%1, %2};" : "=l"(r) : "f"(a), "f"(b));
  return r;
}

// reduce-scatter over lane bits 0-2: input A[q] = {(b0,b2),(b1,b3)} partials,
// output g[q] = full sum for batch b = s&3 (lanes s and s+4 duplicate).
__device__ __forceinline__ void reduce8(u64 A[4][2], int s, float g[4]) {
  const int keep = s & 1;
  const int e    = (s >> 1) & 1;
  u64 R[4];
#pragma unroll
  for (int q = 0; q < 4; ++q) {
    u64 sent = keep ? A[q][0] : A[q][1];
    u64 kept = keep ? A[q][1] : A[q][0];
    R[q] = add2(kept, shfl64x(sent, 1));
  }
#pragma unroll
  for (int q = 0; q < 4; ++q) {
    float lo, hi;
    unpack2(R[q], lo, hi);
    float sendv = e ? lo : hi;
    float keepv = e ? hi : lo;
    g[q] = keepv + __shfl_xor_sync(0xffffffffu, sendv, 2);
  }
#pragma unroll
  for (int q = 0; q < 4; ++q) g[q] += __shfl_xor_sync(0xffffffffu, g[q], 4);
}
}  // namespace

__global__ __launch_bounds__(NTHR, 1) void lstm2_rs_kernel(
    const float* __restrict__ x,
    const float* __restrict__ Wih0, const float* __restrict__ Whh0,
    const float* __restrict__ bih0, const float* __restrict__ bhh0,
    const float* __restrict__ Wih1, const float* __restrict__ Whh1,
    const float* __restrict__ bih1, const float* __restrict__ bhh1,
    const float* __restrict__ fcw, const float* __restrict__ fcb,
    float* __restrict__ out) {
  // hcf: 2 buffers x 128 rows x 4 cols, XOR-swizzled rows. cols permuted (b0,b2,b1,b3).
  __shared__ __align__(16) float hcf[2 * 128 * 4];
  __shared__ __align__(16) float xb[2 * IN * NB];  // [buf][i][col]
  __shared__ float4 biasq[2][H];                   // (i,f,g,o) quad per unit
  __shared__ float fcw_s[H];

  const int tid = threadIdx.x;
  const int b0  = blockIdx.x * NB;
  const int j   = tid >> 3;   // unit 0..63  (owns gates j, j+64, j+128, j+192)
  const int s   = tid & 7;    // k-split 0..7
  const int sl  = s & 3;
  const int hi  = s >> 2;
  const int col = ((sl & 1) << 1) | (sl >> 1);  // physical col of batch b=sl

  // ---- register-resident weights: 100 floats ----
  float w0[4][8], wx[4], w1[4][16];
  {
    const float* base1 = hi ? Whh1 : Wih1;
#pragma unroll
    for (int q = 0; q < 4; ++q) {
      const int g = q * 64 + j;
#pragma unroll
      for (int kk = 0; kk < 8; ++kk) w0[q][kk] = Whh0[g * H + s * 8 + kk];
      wx[q] = Wih0[g * IN + s];
#pragma unroll
      for (int kk = 0; kk < 16; ++kk) w1[q][kk] = base1[g * H + sl * 16 + kk];
    }
  }

  // ---- shared staging ----
  for (int idx = tid; idx < 2 * 128 * 4; idx += NTHR) hcf[idx] = 0.0f;
  if (tid < 2 * H) {
    const int l = tid >> 6, jj = tid & 63;
    const float* bi = l ? bih1 : bih0;
    const float* bh = l ? bhh1 : bhh0;
    biasq[l][jj] = make_float4(bi[jj] + bh[jj], bi[64 + jj] + bh[64 + jj],
                               bi[128 + jj] + bh[128 + jj], bi[192 + jj] + bh[192 + jj]);
  }
  if (tid < H) fcw_s[tid] = fcw[tid];
  if (tid < NB * IN) {  // x[t=0] into buffer 0, permuted cols
    const int b = tid >> 3, i = tid & 7;
    const int ci = ((b & 1) << 1) | (b >> 1);
    xb[i * 4 + ci] = x[(b0 + b) * Tlen * IN + i];
  }
  __syncthreads();

  // ---- per-thread addresses (float indices), toggled per step ----
  const int s2 = s << 2;
  int rd0 = s * 32;                                   // l0 read (buf cur=0)
  int xr  = s * 4;                                    // x read (buf 0)
  int l1b = (hi ? 0 : 512) + hi * 256 + sl * 64;      // l1 read (s<4: buf nxt; s>=4: buf cur)
  const int xlo = ((2 * sl) ^ hi) << 2;               // l1 swizzle const
  int wh0 = 512 + ((j << 2) ^ (((j >> 3) & 7) << 2)) + col;              // h0 write (buf nxt)
  int wh1 = 512 + 256 + ((j << 2) ^ ((((j >> 3) ^ 1) & 7) << 2)) + col;  // h1 write
  int xw  = 32 + (tid & 7) * 4 + ((((tid >> 3) & 1) << 1) | ((tid >> 4) & 1));  // loader only
  long xg = (long)(b0 + (tid >> 3)) * Tlen * IN + (tid & 7) + IN;  // x[t+1] gmem idx

  float c0 = 0.0f, c1 = 0.0f;

#pragma unroll 1
  for (int t = 0; t < Tlen; ++t) {
    float xn = 0.0f;
    const bool ld = (tid < NB * IN) && (t + 1 < Tlen);
    if (ld) xn = __ldg(&x[xg]);
    xg += IN;

    // ============ layer 0 ============
    u64 A[4][2] = {{0, 0}, {0, 0}, {0, 0}, {0, 0}};
    {
      ulonglong2 v = *reinterpret_cast<const ulonglong2*>(&xb[xr]);
#pragma unroll
      for (int q = 0; q < 4; ++q) {
        u64 W = splat2(wx[q]);
        ffma2(A[q][0], W, v.x);
        ffma2(A[q][1], W, v.y);
      }
    }
#pragma unroll
    for (int kk = 0; kk < 8; ++kk) {
      ulonglong2 v =
          *reinterpret_cast<const ulonglong2*>(&hcf[rd0 + ((kk << 2) ^ s2)]);
#pragma unroll
      for (int q = 0; q < 4; ++q) {
        u64 W = splat2(w0[q][kk]);
        ffma2(A[q][0], W, v.x);
        ffma2(A[q][1], W, v.y);
      }
    }
    {
      float g[4];
      reduce8(A, s, g);
      float4 bq = biasq[0][j];
      float gi = sigmoid_fast(g[0] + bq.x);
      float gf = sigmoid_fast(g[1] + bq.y);
      float gg = tanh_fast(g[2] + bq.z);
      float go = sigmoid_fast(g[3] + bq.w);
      c0 = fmaf(gf, c0, gi * gg);
      if (s < 4) hcf[wh0] = go * tanh_fast(c0);
    }
    __syncthreads();

    // ============ layer 1 ============
    u64 D[4][2] = {{0, 0}, {0, 0}, {0, 0}, {0, 0}};
#pragma unroll
    for (int kk = 0; kk < 16; ++kk) {
      const int imm = (kk << 2) ^ ((kk >> 3) << 2);  // compile-time
      ulonglong2 v =
          *reinterpret_cast<const ulonglong2*>(&hcf[l1b + (imm ^ xlo)]);
#pragma unroll
      for (int q = 0; q < 4; ++q) {
        u64 W = splat2(w1[q][kk]);
        ffma2(D[q][0], W, v.x);
        ffma2(D[q][1], W, v.y);
      }
    }
    if (ld) xb[xw] = xn;
    {
      float g[4];
      reduce8(D, s, g);
      float4 bq = biasq[1][j];
      float gi = sigmoid_fast(g[0] + bq.x);
      float gf = sigmoid_fast(g[1] + bq.y);
      float gg = tanh_fast(g[2] + bq.z);
      float go = sigmoid_fast(g[3] + bq.w);
      c1 = fmaf(gf, c1, gi * gg);
      if (s < 4) hcf[wh1] = go * tanh_fast(c1);
    }
    __syncthreads();

    rd0 ^= 512; l1b ^= 512; wh0 ^= 512; wh1 ^= 512; xr ^= 32; xw ^= 32;
  }

  // ---- epilogue: FC + sigmoid on final h1 (buffer 0, rows 64..127) ----
  if (tid < NB) {
    const int ci = ((tid & 1) << 1) | (tid >> 1);
    float acc = fcb[0];
#pragma unroll 16
    for (int jj = 0; jj < H; ++jj) {
      const int idx = 256 + ((jj << 2) ^ ((((jj >> 3) ^ 1) & 7) << 2)) + ci;
      acc = fmaf(hcf[idx], fcw_s[jj], acc);
    }
    out[b0 + tid] = 1.0f / (1.0f + __expf(-acc));
  }
}

extern "C" void kernel_launch(void* const* d_in, const int* in_sizes, int n_in,
                              void* d_out, int out_size) {
  const float* x    = (const float*)d_in[0];
  const float* Wih0 = (const float*)d_in[1];
  const float* Whh0 = (const float*)d_in[2];
  const float* bih0 = (const float*)d_in[3];
  const float* bhh0 = (const float*)d_in[4];
  const float* Wih1 = (const float*)d_in[5];
  const float* Whh1 = (const float*)d_in[6];
  const float* bih1 = (const float*)d_in[7];
  const float* bhh1 = (const float*)d_in[8];
  const float* fcw  = (const float*)d_in[9];
  const float* fcb  = (const float*)d_in[10];
  float* out = (float*)d_out;

  lstm2_rs_kernel<<<NBLK, NTHR>>>(x, Wih0, Whh0, bih0, bhh0, Wih1, Whh1,
                                  bih1, bhh1, fcw, fcb, out);
}

// round 6
// speedup vs baseline: 2.5319x; 1.1282x over previous
#include <cuda_runtime.h>

namespace {
constexpr int Bsz  = 512;
constexpr int Tlen = 4096;
constexpr int IN   = 8;
constexpr int H    = 64;
constexpr int NB   = 4;
constexpr int NTHR = 512;        // 128 gate-pairs x 4 k-splits
constexpr int NBLK = Bsz / NB;   // 128

using u64 = unsigned long long;

__device__ __forceinline__ float tanh_fast(float x) {
  float y;
  asm("tanh.approx.f32 %0, %1;" : "=f"(y) : "f"(x));
  return y;
}
__device__ __forceinline__ float sigmoid_fast(float x) {
  return fmaf(0.5f, tanh_fast(0.5f * x), 0.5f);
}
__device__ __forceinline__ u64 splat2(float w) {
  u64 r;
  asm("mov.b64 %0, {%1, %1};" : "=l"(r) : "f"(w));
  return r;
}
__device__ __forceinline__ void ffma2(u64& acc, u64 a, u64 b) {
  asm("fma.rn.f32x2 %0, %1, %2, %0;" : "+l"(acc) : "l"(a), "l"(b));
}
__device__ __forceinline__ void unpack2(u64 v, float& lo, float& hi) {
  asm("mov.b64 {%0, %1}, %2;" : "=f"(lo), "=f"(hi) : "l"(v));
}
}  // namespace

__global__ __launch_bounds__(NTHR, 1) void lstm2_sched_kernel(
    const float* __restrict__ x,
    const float* __restrict__ Wih0, const float* __restrict__ Whh0,
    const float* __restrict__ bih0, const float* __restrict__ bhh0,
    const float* __restrict__ Wih1, const float* __restrict__ Whh1,
    const float* __restrict__ bih1, const float* __restrict__ bhh1,
    const float* __restrict__ fcw, const float* __restrict__ fcb,
    float* __restrict__ out) {
  __shared__ __align__(16) float h0s[H][NB];         // single-buffered (barrier-separated)
  __shared__ __align__(16) float h1s[H][NB];
  __shared__ __align__(16) float part0[4][NB][256];  // l0 gate partials (written [A], read [B])
  __shared__ __align__(16) float part1[4][NB][256];  // l1 gate partials (written [B], read [A])
  __shared__ __align__(16) float xb[IN][NB];         // x[t] slice (written [B], read [A])
  __shared__ float4 biasq[2][H];
  __shared__ float fcw_s[H];

  const int tid = threadIdx.x;
  const int b0  = blockIdx.x * NB;
  const int gp  = tid & 127;       // gate pair: gates gp, gp+128
  const int s   = tid >> 7;        // k-split 0..3
  const bool low = (tid < 256);    // s in {0,1}

  // ---- register-resident weights (100 floats) ----
  float w0[2][16], wx[2][2], w1[2][32];
  {
    const float* base1 = low ? Wih1 : Whh1;  // s01: Wih1 (vs h0); s23: Whh1 (vs h1)
#pragma unroll
    for (int q = 0; q < 2; ++q) {
      const int g = gp + q * 128;
#pragma unroll
      for (int kk = 0; kk < 16; ++kk) w0[q][kk] = Whh0[g * H + s * 16 + kk];
#pragma unroll
      for (int ii = 0; ii < 2; ++ii) wx[q][ii] = Wih0[g * IN + s * 2 + ii];
#pragma unroll
      for (int kk = 0; kk < 32; ++kk) w1[q][kk] = base1[g * H + (s & 1) * 32 + kk];
    }
  }

  // ---- staging ----
  if (tid < 2 * H) {
    const int l = tid >> 6, jj = tid & 63;
    const float* bi = l ? bih1 : bih0;
    const float* bh = l ? bhh1 : bhh0;
    biasq[l][jj] = make_float4(bi[jj] + bh[jj], bi[64 + jj] + bh[64 + jj],
                               bi[128 + jj] + bh[128 + jj], bi[192 + jj] + bh[192 + jj]);
  }
  if (tid >= 128 && tid < 128 + H) fcw_s[tid - 128] = fcw[tid - 128];
  if (tid >= 192 && tid < 192 + 2 * H) {  // zero h0s, h1s
    const int r = tid - 192;
    *reinterpret_cast<float4*>(r < H ? &h0s[r][0] : &h1s[r - H][0]) =
        make_float4(0.f, 0.f, 0.f, 0.f);
  }
  const bool isLoader = (tid >= 256 && tid < 256 + NB * IN);
  const int li = tid - 256;                 // loader index: b = li>>3, i = li&7
  if (isLoader) {  // x[t=0]
    xb[li & 7][li >> 3] = x[(b0 + (li >> 3)) * Tlen * IN + (li & 7)];
  }
  long xg = isLoader
                ? (long)(b0 + (li >> 3)) * Tlen * IN + IN + (li & 7)
                : 0;
  __syncthreads();

  const int pj = tid & 63;   // pointwise unit (low threads)
  const int pb = tid >> 6;   // pointwise batch (low threads)
  float c0 = 0.0f, c1 = 0.0f;

#pragma unroll 1
  for (int t = 0; t < Tlen; ++t) {
    // ================= phase [A] =================
    float xn = 0.0f;
    if (isLoader && t + 1 < Tlen) {
      xn = __ldg(&x[xg]);
      xg += IN;
    }
    if (low && t > 0) {  // pointwise h1(t-1)
      float4 bq = biasq[1][pj];
      float gi = bq.x + part1[0][pb][pj] + part1[1][pb][pj] + part1[2][pb][pj] + part1[3][pb][pj];
      float gf = bq.y + part1[0][pb][H + pj] + part1[1][pb][H + pj] + part1[2][pb][H + pj] + part1[3][pb][H + pj];
      float gg = bq.z + part1[0][pb][2 * H + pj] + part1[1][pb][2 * H + pj] + part1[2][pb][2 * H + pj] + part1[3][pb][2 * H + pj];
      float go = bq.w + part1[0][pb][3 * H + pj] + part1[1][pb][3 * H + pj] + part1[2][pb][3 * H + pj] + part1[3][pb][3 * H + pj];
      gi = sigmoid_fast(gi); gf = sigmoid_fast(gf);
      gg = tanh_fast(gg);    go = sigmoid_fast(go);
      c1 = fmaf(gf, c1, gi * gg);
      h1s[pj][pb] = go * tanh_fast(c1);
    }
    // l0 partials (all threads): gates0(t) from h0(t-1), x(t)
    {
      u64 A[2][2] = {{0, 0}, {0, 0}};
#pragma unroll
      for (int ii = 0; ii < 2; ++ii) {
        ulonglong2 v = *reinterpret_cast<const ulonglong2*>(&xb[s * 2 + ii][0]);
#pragma unroll
        for (int q = 0; q < 2; ++q) {
          u64 W = splat2(wx[q][ii]);
          ffma2(A[q][0], W, v.x);
          ffma2(A[q][1], W, v.y);
        }
      }
#pragma unroll
      for (int kk = 0; kk < 16; ++kk) {
        ulonglong2 v = *reinterpret_cast<const ulonglong2*>(&h0s[s * 16 + kk][0]);
#pragma unroll
        for (int q = 0; q < 2; ++q) {
          u64 W = splat2(w0[q][kk]);
          ffma2(A[q][0], W, v.x);
          ffma2(A[q][1], W, v.y);
        }
      }
#pragma unroll
      for (int q = 0; q < 2; ++q) {
        float v0, v1, v2, v3;
        unpack2(A[q][0], v0, v1);
        unpack2(A[q][1], v2, v3);
        const int g = gp + q * 128;
        part0[s][0][g] = v0; part0[s][1][g] = v1;
        part0[s][2][g] = v2; part0[s][3][g] = v3;
      }
    }
    __syncthreads();

    // ================= phase [B] =================
    if (low) {  // pointwise h0(t), then Wih1@h0(t) partials
      float4 bq = biasq[0][pj];
      float gi = bq.x + part0[0][pb][pj] + part0[1][pb][pj] + part0[2][pb][pj] + part0[3][pb][pj];
      float gf = bq.y + part0[0][pb][H + pj] + part0[1][pb][H + pj] + part0[2][pb][H + pj] + part0[3][pb][H + pj];
      float gg = bq.z + part0[0][pb][2 * H + pj] + part0[1][pb][2 * H + pj] + part0[2][pb][2 * H + pj] + part0[3][pb][2 * H + pj];
      float go = bq.w + part0[0][pb][3 * H + pj] + part0[1][pb][3 * H + pj] + part0[2][pb][3 * H + pj] + part0[3][pb][3 * H + pj];
      gi = sigmoid_fast(gi); gf = sigmoid_fast(gf);
      gg = tanh_fast(gg);    go = sigmoid_fast(go);
      c0 = fmaf(gf, c0, gi * gg);
      h0s[pj][pb] = go * tanh_fast(c0);
      asm volatile("bar.sync 1, 256;" ::: "memory");  // h0(t) complete among low threads
    } else if (isLoader && t + 1 < Tlen) {
      xb[li & 7][li >> 3] = xn;  // stage x(t+1); read next [A] (after barrier)
    }
    {
      const float(*hs)[NB] = low ? h0s : h1s;  // s01: h0(t); s23: h1(t-1)
      const int rb = (s & 1) * 32;
      u64 D[2][2] = {{0, 0}, {0, 0}};
#pragma unroll
      for (int kk = 0; kk < 32; ++kk) {
        ulonglong2 v = *reinterpret_cast<const ulonglong2*>(&hs[rb + kk][0]);
#pragma unroll
        for (int q = 0; q < 2; ++q) {
          u64 W = splat2(w1[q][kk]);
          ffma2(D[q][0], W, v.x);
          ffma2(D[q][1], W, v.y);
        }
      }
#pragma unroll
      for (int q = 0; q < 2; ++q) {
        float v0, v1, v2, v3;
        unpack2(D[q][0], v0, v1);
        unpack2(D[q][1], v2, v3);
        const int g = gp + q * 128;
        part1[s][0][g] = v0; part1[s][1][g] = v1;
        part1[s][2][g] = v2; part1[s][3][g] = v3;
      }
    }
    __syncthreads();
  }

  // ---- epilogue: final pointwise h1(T-1), then FC + sigmoid ----
  if (low) {
    float4 bq = biasq[1][pj];
    float gi = bq.x + part1[0][pb][pj] + part1[1][pb][pj] + part1[2][pb][pj] + part1[3][pb][pj];
    float gf = bq.y + part1[0][pb][H + pj] + part1[1][pb][H + pj] + part1[2][pb][H + pj] + part1[3][pb][H + pj];
    float gg = bq.z + part1[0][pb][2 * H + pj] + part1[1][pb][2 * H + pj] + part1[2][pb][2 * H + pj] + part1[3][pb][2 * H + pj];
    float go = bq.w + part1[0][pb][3 * H + pj] + part1[1][pb][3 * H + pj] + part1[2][pb][3 * H + pj] + part1[3][pb][3 * H + pj];
    gi = sigmoid_fast(gi); gf = sigmoid_fast(gf);
    gg = tanh_fast(gg);    go = sigmoid_fast(go);
    c1 = fmaf(gf, c1, gi * gg);
    h1s[pj][pb] = go * tanh_fast(c1);
  }
  __syncthreads();
  if (tid < NB) {
    float acc = fcb[0];
#pragma unroll 16
    for (int jj = 0; jj < H; ++jj) acc = fmaf(h1s[jj][tid], fcw_s[jj], acc);
    out[b0 + tid] = 1.0f / (1.0f + __expf(-acc));
  }
}

extern "C" void kernel_launch(void* const* d_in, const int* in_sizes, int n_in,
                              void* d_out, int out_size) {
  const float* x    = (const float*)d_in[0];
  const float* Wih0 = (const float*)d_in[1];
  const float* Whh0 = (const float*)d_in[2];
  const float* bih0 = (const float*)d_in[3];
  const float* bhh0 = (const float*)d_in[4];
  const float* Wih1 = (const float*)d_in[5];
  const float* Whh1 = (const float*)d_in[6];
  const float* bih1 = (const float*)d_in[7];
  const float* bhh1 = (const float*)d_in[8];
  const float* fcw  = (const float*)d_in[9];
  const float* fcb  = (const float*)d_in[10];
  float* out = (float*)d_out;

  lstm2_sched_kernel<<<NBLK, NTHR>>>(x, Wih0, Whh0, bih0, bhh0, Wih1, Whh1,
                                     bih1, bhh1, fcw, fcb, out);
}

// round 10
// speedup vs baseline: 7.5832x; 2.9950x over previous
#include <cuda_runtime.h>
#include <cuda_fp16.h>
#include <cstdint>

namespace {
constexpr int Tlen = 4096;
constexpr int IN   = 8;
constexpr int H    = 64;
constexpr int NB   = 4;
constexpr int NTHR = 512;   // 16 mma warps; threads 0..255 also do pointwise
constexpr int NBLK = 128;

using u32 = unsigned int;

constexpr int PB0 = 88;   // halves per row of B0 hT (176 B pitch): k = 0..79
constexpr int PB1 = 136;  // halves per row of B1 hT (272 B pitch): k = 0..127
constexpr int GST = 12;   // gate array column stride (floats), conflict-free

__device__ __forceinline__ float tanh_fast(float x) {
  float y;
  asm("tanh.approx.f32 %0, %1;" : "=f"(y) : "f"(x));
  return y;
}
__device__ __forceinline__ float sigmoid_fast(float x) {
  return fmaf(0.5f, tanh_fast(0.5f * x), 0.5f);
}
__device__ __forceinline__ u32 smem_u32(const void* p) {
  u32 a;
  asm("{ .reg .u64 t; cvta.to.shared.u64 t, %1; cvt.u32.u64 %0, t; }" : "=r"(a) : "l"(p));
  return a;
}
__device__ __forceinline__ void ldsm_x2(u32& r0, u32& r1, u32 addr) {
  asm volatile("ldmatrix.sync.aligned.m8n8.x2.shared.b16 {%0,%1}, [%2];"
               : "=r"(r0), "=r"(r1) : "r"(addr));
}
__device__ __forceinline__ void mma16816(float& c0, float& c1, float& c2, float& c3,
                                         u32 a0, u32 a1, u32 a2, u32 a3,
                                         u32 b0, u32 b1) {
  asm volatile(
      "mma.sync.aligned.m16n8k16.row.col.f32.f16.f16.f32 "
      "{%0,%1,%2,%3}, {%4,%5,%6,%7}, {%8,%9}, {%0,%1,%2,%3};"
      : "+f"(c0), "+f"(c1), "+f"(c2), "+f"(c3)
      : "r"(a0), "r"(a1), "r"(a2), "r"(a3), "r"(b0), "r"(b1));
}
__device__ __forceinline__ u32 pack2(float lo, float hi) {
  __half2 h = __floats2half2_rn(lo, hi);
  return *reinterpret_cast<u32*>(&h);
}
}  // namespace

__global__ __launch_bounds__(NTHR, 1) void lstm2_hmma_kernel(
    const float* __restrict__ x,
    const float* __restrict__ Wih0, const float* __restrict__ Whh0,
    const float* __restrict__ bih0, const float* __restrict__ bhh0,
    const float* __restrict__ Wih1, const float* __restrict__ Whh1,
    const float* __restrict__ bih1, const float* __restrict__ bhh1,
    const float* __restrict__ fcw, const float* __restrict__ fcb,
    float* __restrict__ out) {
  __shared__ __align__(16) unsigned short B0[8 * PB0];  // hT0: [n][k] k: 0-63 h0, 64-71 x, 72-79 zero
  __shared__ __align__(16) unsigned short B1[8 * PB1];  // hT1: [n][k] k: 0-63 h0, 64-127 h1
  __shared__ __align__(16) float G0[256 * GST];         // gates0(t)
  __shared__ __align__(16) float G1[256 * GST];         // gates1(t-1)
  __shared__ float H1F[256];                            // final h1 fp32 [j*4+b]
  __shared__ float FCW[H];

  const int tid  = threadIdx.x;
  const int w    = tid >> 5;
  const int lane = tid & 31;
  const int b0   = blockIdx.x * NB;

  // ---- zero B buffers ----
  for (int i = tid; i < 8 * PB0; i += NTHR) B0[i] = 0;
  for (int i = tid; i < 8 * PB1; i += NTHR) B1[i] = 0;
  if (tid < H) FCW[tid] = fcw[tid];

  // ---- register-resident A fragments (fp16), warp w owns m-tile w of l0 and l1 ----
  // A frag reg mapping (m16n8k16 row-major): reg0={(r,c),(r,c+1)} reg1={(r+8,c),(r+8,c+1)}
  //                                          reg2={(r,c+8),(r,c+9)} reg3={(r+8,c+8),(r+8,c+9)}
  u32 A0f[5][4], A1f[8][4];
  {
    const int r = w * 16 + (lane >> 2);     // gate row (and r+8)
    const int cq = (lane & 3) * 2;
    auto a0e = [&](int g, int k) -> float {
      if (k < 64) return Whh0[g * H + k];
      if (k < 72) return Wih0[g * IN + (k - 64)];
      return 0.0f;
    };
    auto a1e = [&](int g, int k) -> float {
      return (k < 64) ? Wih1[g * H + k] : Whh1[g * H + (k - 64)];
    };
#pragma unroll
    for (int kf = 0; kf < 5; ++kf) {
      const int c = kf * 16 + cq;
      A0f[kf][0] = pack2(a0e(r, c),         a0e(r, c + 1));
      A0f[kf][1] = pack2(a0e(r + 8, c),     a0e(r + 8, c + 1));
      A0f[kf][2] = pack2(a0e(r, c + 8),     a0e(r, c + 9));
      A0f[kf][3] = pack2(a0e(r + 8, c + 8), a0e(r + 8, c + 9));
    }
#pragma unroll
    for (int kf = 0; kf < 8; ++kf) {
      const int c = kf * 16 + cq;
      A1f[kf][0] = pack2(a1e(r, c),         a1e(r, c + 1));
      A1f[kf][1] = pack2(a1e(r + 8, c),     a1e(r + 8, c + 1));
      A1f[kf][2] = pack2(a1e(r, c + 8),     a1e(r, c + 9));
      A1f[kf][3] = pack2(a1e(r + 8, c + 8), a1e(r + 8, c + 9));
    }
  }

  // ---- pointwise constants (threads 0..255): biases ----
  const int pj = tid >> 2, pb = tid & 3;
  float bs0[4], bs1[4];
  if (tid < 256) {
#pragma unroll
    for (int q = 0; q < 4; ++q) {
      const int g = q * 64 + pj;
      bs0[q] = bih0[g] + bhh0[g];
      bs1[q] = bih1[g] + bhh1[g];
    }
  }

  // ---- x loader = warp 8 (tid 256..287): b = l>>3, i = l&7 ----
  const bool isLoader = (tid >= 256 && tid < 288);
  const int ll = tid - 256;
  if (isLoader) {  // stage x(0)
    float v = x[(long)(b0 + (ll >> 3)) * Tlen * IN + (ll & 7)];
    B0[(ll >> 3) * PB0 + 64 + (ll & 7)] = __half_as_ushort(__float2half_rn(v));
  }
  long xg = isLoader ? ((long)(b0 + (ll >> 3)) * Tlen * IN + IN + (ll & 7)) : 0;
  __syncthreads();

  // ---- per-thread smem addresses ----
  const u32 b0base = smem_u32(B0) + (lane & 7) * (PB0 * 2) + ((lane >> 3) & 1) * 16;
  const u32 b1base = smem_u32(B1) + (lane & 7) * (PB1 * 2) + ((lane >> 3) & 1) * 16;
  const int crow = w * 16 + (lane >> 2);
  const int ccol = (lane & 3) * 2;
  const bool cact = (lane & 3) < 2;  // cols 0..3 = real batches
  float* g0p = &G0[crow * GST + ccol];
  float* g1p = &G1[crow * GST + ccol];

  float c0s = 0.0f, c1s = 0.0f;

#pragma unroll 1
  for (int t = 0; t <= Tlen; ++t) {
    // prefetch x(t+1)
    float xn = 0.0f;
    if (isLoader && t + 1 < Tlen) {
      xn = __ldg(&x[xg]);
      xg += IN;
    }

    // ================= phase A: MMAs =================
    // l0: gates0(t) = [Whh0|Wih0] @ [h0(t-1); x(t)]
    {
      float d0 = 0.f, d1 = 0.f, d2 = 0.f, d3 = 0.f;
#pragma unroll
      for (int kf = 0; kf < 5; ++kf) {
        u32 br0, br1;
        ldsm_x2(br0, br1, b0base + kf * 32);
        mma16816(d0, d1, d2, d3, A0f[kf][0], A0f[kf][1], A0f[kf][2], A0f[kf][3], br0, br1);
      }
      if (cact) {
        *reinterpret_cast<float2*>(g0p) = make_float2(d0, d1);
        *reinterpret_cast<float2*>(g0p + 8 * GST) = make_float2(d2, d3);
      }
    }
    // l1: gates1(t-1) = [Wih1|Whh1] @ [h0(t-1); h1(t-2)]
    {
      float d0 = 0.f, d1 = 0.f, d2 = 0.f, d3 = 0.f;
#pragma unroll
      for (int kf = 0; kf < 8; ++kf) {
        u32 br0, br1;
        ldsm_x2(br0, br1, b1base + kf * 32);
        mma16816(d0, d1, d2, d3, A1f[kf][0], A1f[kf][1], A1f[kf][2], A1f[kf][3], br0, br1);
      }
      if (cact) {
        *reinterpret_cast<float2*>(g1p) = make_float2(d0, d1);
        *reinterpret_cast<float2*>(g1p + 8 * GST) = make_float2(d2, d3);
      }
    }
    __syncthreads();

    // ================= phase B: pointwise =================
    if (tid < 256) {
      if (t > 0) {  // h1(t-1) from gates1(t-1)
        float gi = sigmoid_fast(G1[(pj)       * GST + pb] + bs1[0]);
        float gf = sigmoid_fast(G1[(64 + pj)  * GST + pb] + bs1[1]);
        float gg = tanh_fast(   G1[(128 + pj) * GST + pb] + bs1[2]);
        float go = sigmoid_fast(G1[(192 + pj) * GST + pb] + bs1[3]);
        c1s = fmaf(gf, c1s, gi * gg);
        float h1v = go * tanh_fast(c1s);
        if (t < Tlen) {
          B1[pb * PB1 + 64 + pj] = __half_as_ushort(__float2half_rn(h1v));
        } else {
          H1F[pj * 4 + pb] = h1v;
        }
      }
      if (t < Tlen) {  // h0(t) from gates0(t)
        float gi = sigmoid_fast(G0[(pj)       * GST + pb] + bs0[0]);
        float gf = sigmoid_fast(G0[(64 + pj)  * GST + pb] + bs0[1]);
        float gg = tanh_fast(   G0[(128 + pj) * GST + pb] + bs0[2]);
        float go = sigmoid_fast(G0[(192 + pj) * GST + pb] + bs0[3]);
        c0s = fmaf(gf, c0s, gi * gg);
        float h0v = go * tanh_fast(c0s);
        unsigned short hb = __half_as_ushort(__float2half_rn(h0v));
        B0[pb * PB0 + pj] = hb;  // l0 B (next step)
        B1[pb * PB1 + pj] = hb;  // l1 B rows 0..63
      }
    } else if (isLoader && t + 1 < Tlen) {
      B0[(ll >> 3) * PB0 + 64 + (ll & 7)] = __half_as_ushort(__float2half_rn(xn));
    }
    __syncthreads();
  }

  // ---- FC epilogue ----
  if (tid < NB) {
    float acc = fcb[0];
#pragma unroll 16
    for (int j = 0; j < H; ++j) acc = fmaf(H1F[j * 4 + tid], FCW[j], acc);
    out[b0 + tid] = 1.0f / (1.0f + __expf(-acc));
  }
}

extern "C" void kernel_launch(void* const* d_in, const int* in_sizes, int n_in,
                              void* d_out, int out_size) {
  const float* x    = (const float*)d_in[0];
  const float* Wih0 = (const float*)d_in[1];
  const float* Whh0 = (const float*)d_in[2];
  const float* bih0 = (const float*)d_in[3];
  const float* bhh0 = (const float*)d_in[4];
  const float* Wih1 = (const float*)d_in[5];
  const float* Whh1 = (const float*)d_in[6];
  const float* bih1 = (const float*)d_in[7];
  const float* bhh1 = (const float*)d_in[8];
  const float* fcw  = (const float*)d_in[9];
  const float* fcb  = (const float*)d_in[10];
  float* out = (float*)d_out;

  lstm2_hmma_kernel<<<NBLK, NTHR>>>(x, Wih0, Whh0, bih0, bhh0, Wih1, Whh1,
                                    bih1, bhh1, fcw, fcb, out);
}

// round 11
// speedup vs baseline: 7.8028x; 1.0290x over previous
#include <cuda_runtime.h>
#include <cuda_fp16.h>
#include <cstdint>

namespace {
constexpr int Tlen = 4096;
constexpr int IN   = 8;
constexpr int H    = 64;
constexpr int NB   = 4;
constexpr int NTHR = 512;   // 16 warps, all do MMA + pointwise
constexpr int NBLK = 128;

using u32 = unsigned int;

constexpr int PB0 = 88;   // halves per row of B0 hT (176 B pitch): k 0..79
constexpr int PB1 = 136;  // halves per row of B1 hT (272 B pitch): k 0..127

__device__ __forceinline__ float tanh_fast(float x) {
  float y;
  asm("tanh.approx.f32 %0, %1;" : "=f"(y) : "f"(x));
  return y;
}
__device__ __forceinline__ float sigmoid_fast(float x) {
  return fmaf(0.5f, tanh_fast(0.5f * x), 0.5f);
}
__device__ __forceinline__ u32 smem_u32(const void* p) {
  u32 a;
  asm("{ .reg .u64 t; cvta.to.shared.u64 t, %1; cvt.u32.u64 %0, t; }" : "=r"(a) : "l"(p));
  return a;
}
__device__ __forceinline__ void ldsm_x2(u32& r0, u32& r1, u32 addr) {
  asm volatile("ldmatrix.sync.aligned.m8n8.x2.shared.b16 {%0,%1}, [%2];"
               : "=r"(r0), "=r"(r1) : "r"(addr));
}
__device__ __forceinline__ void mma16816(float& c0, float& c1, float& c2, float& c3,
                                         u32 a0, u32 a1, u32 a2, u32 a3,
                                         u32 b0, u32 b1) {
  asm volatile(
      "mma.sync.aligned.m16n8k16.row.col.f32.f16.f16.f32 "
      "{%0,%1,%2,%3}, {%4,%5,%6,%7}, {%8,%9}, {%0,%1,%2,%3};"
      : "+f"(c0), "+f"(c1), "+f"(c2), "+f"(c3)
      : "r"(a0), "r"(a1), "r"(a2), "r"(a3), "r"(b0), "r"(b1));
}
__device__ __forceinline__ u32 pack2(float lo, float hi) {
  __half2 h = __floats2half2_rn(lo, hi);
  return *reinterpret_cast<u32*>(&h);
}
}  // namespace

__global__ __launch_bounds__(NTHR, 1) void lstm2_hmma2_kernel(
    const float* __restrict__ x,
    const float* __restrict__ Wih0, const float* __restrict__ Whh0,
    const float* __restrict__ bih0, const float* __restrict__ bhh0,
    const float* __restrict__ Wih1, const float* __restrict__ Whh1,
    const float* __restrict__ bih1, const float* __restrict__ bhh1,
    const float* __restrict__ fcw, const float* __restrict__ fcb,
    float* __restrict__ out) {
  __shared__ __align__(16) unsigned short B0[2][8 * PB0];  // [buf][n][k] k: 0-63 h0, 64-71 x
  __shared__ __align__(16) unsigned short B1[2][8 * PB1];  // [buf][n][k] k: 0-63 h0, 64-127 h1
  __shared__ __align__(16) float GW[16][2][4][4][4];       // [warp][layer][u][col][gate]
  __shared__ float H1F[256];                               // final h1 [j*4+b]
  __shared__ float FCW[H];

  const int tid  = threadIdx.x;
  const int w    = tid >> 5;
  const int lane = tid & 31;
  const int b0   = blockIdx.x * NB;
  const int rq   = lane >> 2;          // C/A frag row (and rq+8)
  const int cq   = (lane & 3) * 2;     // frag col pair

  // ---- zero B buffers ----
  for (int i = tid; i < 2 * 8 * PB0; i += NTHR) (&B0[0][0])[i] = 0;
  for (int i = tid; i < 2 * 8 * PB1; i += NTHR) (&B1[0][0])[i] = 0;
  if (tid < H) FCW[tid] = fcw[tid];

  // ---- A fragments, gate-interleaved row order: tile row r = u*4 + gate ----
  u32 A0f[5][4], A1f[8][4];
  {
    auto wrow = [&](int r) { return (r & 3) * 64 + w * 4 + (r >> 2); };  // W row index
    auto a0e = [&](int r, int k) -> float {
      int g = wrow(r);
      if (k < 64) return Whh0[g * H + k];
      if (k < 72) return Wih0[g * IN + (k - 64)];
      return 0.0f;
    };
    auto a1e = [&](int r, int k) -> float {
      int g = wrow(r);
      return (k < 64) ? Wih1[g * H + k] : Whh1[g * H + (k - 64)];
    };
#pragma unroll
    for (int kf = 0; kf < 5; ++kf) {
      const int c = kf * 16 + cq;
      A0f[kf][0] = pack2(a0e(rq, c),         a0e(rq, c + 1));
      A0f[kf][1] = pack2(a0e(rq + 8, c),     a0e(rq + 8, c + 1));
      A0f[kf][2] = pack2(a0e(rq, c + 8),     a0e(rq, c + 9));
      A0f[kf][3] = pack2(a0e(rq + 8, c + 8), a0e(rq + 8, c + 9));
    }
#pragma unroll
    for (int kf = 0; kf < 8; ++kf) {
      const int c = kf * 16 + cq;
      A1f[kf][0] = pack2(a1e(rq, c),         a1e(rq, c + 1));
      A1f[kf][1] = pack2(a1e(rq + 8, c),     a1e(rq + 8, c + 1));
      A1f[kf][2] = pack2(a1e(rq, c + 8),     a1e(rq, c + 9));
      A1f[kf][3] = pack2(a1e(rq + 8, c + 8), a1e(rq + 8, c + 9));
    }
  }

  // ---- per-lane pointwise task: (layer, unit_local, batch) ----
  const int tlayer = lane >> 4;
  const int tu     = (lane >> 2) & 3;
  const int tb     = lane & 3;
  const int tj     = w * 4 + tu;  // global unit
  float4 bq;
  {
    const float* bi = tlayer ? bih1 : bih0;
    const float* bh = tlayer ? bhh1 : bhh0;
    bq = make_float4(bi[tj] + bh[tj], bi[64 + tj] + bh[64 + tj],
                     bi[128 + tj] + bh[128 + tj], bi[192 + tj] + bh[192 + tj]);
  }

  // ---- x loader: warp 15, lane = b*8 + i ----
  const bool isL = (w == 15);
  const int xb_ = lane >> 3, xi = lane & 7;
  const long xbase = (long)(b0 + xb_) * Tlen * IN + xi;
  if (isL) {  // prestage x(0) into buffer 0
    B0[0][xb_ * PB0 + 64 + xi] = __half_as_ushort(__float2half_rn(x[xbase]));
  }
  float xcur = isL ? __ldg(&x[xbase + IN]) : 0.0f;  // x(1)
  __syncthreads();

  // ---- ldsm base addresses (both buffers) ----
  const u32 lrow0 = (lane & 7) * (PB0 * 2) + ((lane >> 3) & 1) * 16;
  const u32 lrow1 = (lane & 7) * (PB1 * 2) + ((lane >> 3) & 1) * 16;
  const u32 sB0a = smem_u32(&B0[0][0]) + lrow0, sB0b = smem_u32(&B0[1][0]) + lrow0;
  const u32 sB1a = smem_u32(&B1[0][0]) + lrow1, sB1b = smem_u32(&B1[1][0]) + lrow1;

  float cst = 0.0f;  // this lane's cell state (c0 if tlayer==0 else c1)
  int cur = 0;

#pragma unroll 1
  for (int t = 0; t <= Tlen; ++t) {
    const int nxt = cur ^ 1;
    // LDG x(t+2) (2-step pipeline)
    float xnext = 0.0f;
    if (isL && t + 2 < Tlen) xnext = __ldg(&x[xbase + (long)(t + 2) * IN]);

    // ---- MMAs: l0 gates(t), l1 gates(t-1) from B[cur] ----
    const u32 a0 = cur ? sB0b : sB0a;
    const u32 a1 = cur ? sB1b : sB1a;
    float d00 = 0.f, d01 = 0.f, d02 = 0.f, d03 = 0.f;
#pragma unroll
    for (int kf = 0; kf < 5; ++kf) {
      u32 br0, br1;
      ldsm_x2(br0, br1, a0 + kf * 32);
      mma16816(d00, d01, d02, d03, A0f[kf][0], A0f[kf][1], A0f[kf][2], A0f[kf][3], br0, br1);
    }
    float d10 = 0.f, d11 = 0.f, d12 = 0.f, d13 = 0.f;
#pragma unroll
    for (int kf = 0; kf < 8; ++kf) {
      u32 br0, br1;
      ldsm_x2(br0, br1, a1 + kf * 32);
      mma16816(d10, d11, d12, d13, A1f[kf][0], A1f[kf][1], A1f[kf][2], A1f[kf][3], br0, br1);
    }

    // ---- in-warp C exchange: [u][col][gate] patch ----
    if ((lane & 3) < 2) {
      const int u = rq >> 2, g = rq & 3;
      GW[w][0][u][cq][g]         = d00;
      GW[w][0][u][cq + 1][g]     = d01;
      GW[w][0][u + 2][cq][g]     = d02;
      GW[w][0][u + 2][cq + 1][g] = d03;
      GW[w][1][u][cq][g]         = d10;
      GW[w][1][u][cq + 1][g]     = d11;
      GW[w][1][u + 2][cq][g]     = d12;
      GW[w][1][u + 2][cq + 1][g] = d13;
    }
    __syncwarp();

    // ---- pointwise: one (layer, unit, batch) per lane ----
    {
      const float4 gv = *reinterpret_cast<const float4*>(&GW[w][tlayer][tu][tb][0]);
      const bool act = tlayer ? (t > 0) : (t < Tlen);
      if (act) {
        float gi = sigmoid_fast(gv.x + bq.x);
        float gf = sigmoid_fast(gv.y + bq.y);
        float gg = tanh_fast(gv.z + bq.z);
        float go = sigmoid_fast(gv.w + bq.w);
        cst = fmaf(gf, cst, gi * gg);
        float hv = go * tanh_fast(cst);
        if (tlayer == 0) {  // h0(t)
          unsigned short hb = __half_as_ushort(__float2half_rn(hv));
          B0[nxt][tb * PB0 + tj] = hb;
          B1[nxt][tb * PB1 + tj] = hb;
        } else {            // h1(t-1)
          if (t < Tlen) {
            B1[nxt][tb * PB1 + 64 + tj] = __half_as_ushort(__float2half_rn(hv));
          } else {
            H1F[tj * 4 + tb] = hv;
          }
        }
      }
    }
    // ---- stage x(t+1) into B[nxt] ----
    if (isL && t + 1 < Tlen) {
      B0[nxt][xb_ * PB0 + 64 + xi] = __half_as_ushort(__float2half_rn(xcur));
      xcur = xnext;
    }
    __syncthreads();
    cur = nxt;
  }

  // ---- FC epilogue ----
  if (tid < NB) {
    float acc = fcb[0];
#pragma unroll 16
    for (int j = 0; j < H; ++j) acc = fmaf(H1F[j * 4 + tid], FCW[j], acc);
    out[b0 + tid] = 1.0f / (1.0f + __expf(-acc));
  }
}

extern "C" void kernel_launch(void* const* d_in, const int* in_sizes, int n_in,
                              void* d_out, int out_size) {
  const float* x    = (const float*)d_in[0];
  const float* Wih0 = (const float*)d_in[1];
  const float* Whh0 = (const float*)d_in[2];
  const float* bih0 = (const float*)d_in[3];
  const float* bhh0 = (const float*)d_in[4];
  const float* Wih1 = (const float*)d_in[5];
  const float* Whh1 = (const float*)d_in[6];
  const float* bih1 = (const float*)d_in[7];
  const float* bhh1 = (const float*)d_in[8];
  const float* fcw  = (const float*)d_in[9];
  const float* fcb  = (const float*)d_in[10];
  float* out = (float*)d_out;

  lstm2_hmma2_kernel<<<NBLK, NTHR>>>(x, Wih0, Whh0, bih0, bhh0, Wih1, Whh1,
                                     bih1, bhh1, fcw, fcb, out);
}